// round 6
// baseline (speedup 1.0000x reference)
#include <cuda_runtime.h>
#include <stdint.h>

#define N_NODES 50000
#define N_EDGES 800000
#define D 64
#define N_LAYERS 12

typedef unsigned long long u64;

__device__ float g_buf0[N_NODES * D];
__device__ float g_buf1[N_NODES * D];
// CSR (built once per launch)
__device__ int  g_deg[N_NODES];
__device__ int  g_row[N_NODES + 1];
__device__ int  g_cur[N_NODES];
__device__ int4 g_edge[N_EDGES];   // {src, dst, w_bits, pad}

// ---------------------------------------------------------------------------
// CSR build: histogram -> scan -> permute (sort edges by dst)
// ---------------------------------------------------------------------------
__global__ void hist_kernel(const int* __restrict__ ei) {
    int e = blockIdx.x * blockDim.x + threadIdx.x;
    if (e < N_EDGES) atomicAdd(&g_deg[ei[N_EDGES + e]], 1);
}

#define SCAN_T 1024
#define SCAN_C 49
__global__ void scan_kernel() {
    __shared__ int part[SCAN_T];
    int t = threadIdx.x;
    int base = t * SCAN_C;
    int s = 0;
#pragma unroll 1
    for (int j = 0; j < SCAN_C; ++j) {
        int idx = base + j;
        if (idx < N_NODES) s += g_deg[idx];
    }
    part[t] = s;
    __syncthreads();
    for (int off = 1; off < SCAN_T; off <<= 1) {
        int v = (t >= off) ? part[t - off] : 0;
        __syncthreads();
        part[t] += v;
        __syncthreads();
    }
    int run = (t > 0) ? part[t - 1] : 0;
#pragma unroll 1
    for (int j = 0; j < SCAN_C; ++j) {
        int idx = base + j;
        if (idx < N_NODES) {
            g_row[idx] = run;
            g_cur[idx] = run;
            run += g_deg[idx];
        }
    }
    if (t == SCAN_T - 1) g_row[N_NODES] = part[SCAN_T - 1];
}

__global__ void permute_kernel(const int* __restrict__ ei,
                               const float* __restrict__ ew) {
    int e = blockIdx.x * blockDim.x + threadIdx.x;
    if (e >= N_EDGES) return;
    int d = ei[N_EDGES + e];
    int pos = atomicAdd(&g_cur[d], 1);
    int4 pk;
    pk.x = ei[e];
    pk.y = d;
    pk.z = __float_as_int(ew[e]);
    pk.w = 0;
    g_edge[pos] = pk;
}

// ---------------------------------------------------------------------------
// f32x2 helpers
// ---------------------------------------------------------------------------
__device__ __forceinline__ u64 fma2(u64 a, u64 b, u64 c) {
    u64 d;
    asm("fma.rn.f32x2 %0, %1, %2, %3;" : "=l"(d) : "l"(a), "l"(b), "l"(c));
    return d;
}
__device__ __forceinline__ u64 bcast2(float x) {
    u64 d;
    asm("mov.b64 %0, {%1, %1};" : "=l"(d) : "f"(x));
    return d;
}
__device__ __forceinline__ u64 pack2(float lo, float hi) {
    u64 d;
    asm("mov.b64 %0, {%1, %2};" : "=l"(d) : "f"(lo), "f"(hi));
    return d;
}
__device__ __forceinline__ float2 unpack2(u64 v) {
    float lo, hi;
    asm("mov.b64 {%0, %1}, %2;" : "=f"(lo), "=f"(hi) : "l"(v));
    return make_float2(lo, hi);
}

// ---------------------------------------------------------------------------
// Fused layer kernel. Per 64-node tile:
//   P0: zero aggr cols of h_s, copy x rows into cols [64,128)
//   P1: edge-parallel CSR-range aggregation (batch-8 gathers, MLP=8,
//       register segmented sum, smem-atomic flush on dst change)
//   P2: in-place l2norm of aggr cols
//   P3: 64x64x128 FFMA2 GEMM + row l2norm + store
// Persistent grid-stride, 256 threads, 3 CTA/SM.
// ---------------------------------------------------------------------------
#define TB 64
#define HSTR 132
#define N_TILES ((N_NODES + TB - 1) / TB)       // 782
#define SMEM_BYTES ((128 * 64 + TB * HSTR) * 4) // 66560 B

__global__ void __launch_bounds__(256, 3)
layer_kernel(const float* __restrict__ xin,
             const float* __restrict__ W,   // [128][64] layer slice
             const float* __restrict__ b,   // [64]
             float* __restrict__ xout) {
    extern __shared__ float smem[];
    float* W_s = smem;             // 128*64
    float* h_s = smem + 128 * 64;  // TB x HSTR

    int tid = threadIdx.x;
    int lane = tid & 31;
    int warp = tid >> 5;

    // Load W slice once per block
    {
        const float4* Wv = reinterpret_cast<const float4*>(W);
        float4* Wsv = reinterpret_cast<float4*>(W_s);
#pragma unroll
        for (int i = 0; i < 8; ++i)
            Wsv[tid + i * 256] = Wv[tid + i * 256];
    }

    int tx = tid & 15, ty = tid >> 4;
    u64 bias0 = pack2(b[tx * 4 + 0], b[tx * 4 + 1]);
    u64 bias1 = pack2(b[tx * 4 + 2], b[tx * 4 + 3]);

    for (int tile = blockIdx.x; tile < N_TILES; tile += gridDim.x) {
        __syncthreads();  // previous tile's GEMM done reading h_s

        int n0 = tile * TB;

        // ---- P0: zero aggr cols [0,64), copy x into cols [64,128)
        {
            int r = tid >> 2;
            int q = tid & 3;
            int node = n0 + r;
            float4 z = make_float4(0.f, 0.f, 0.f, 0.f);
            float4* hz = reinterpret_cast<float4*>(h_s + r * HSTR) + q;
            hz[0] = z; hz[4] = z; hz[8] = z; hz[12] = z;
            float4* hx = reinterpret_cast<float4*>(h_s + r * HSTR + 64) + q;
            if (node < N_NODES) {
                const float4* xr = reinterpret_cast<const float4*>(xin + (size_t)node * D) + q;
                hx[0] = xr[0]; hx[4] = xr[4]; hx[8] = xr[8]; hx[12] = xr[12];
            } else {
                hx[0] = z; hx[4] = z; hx[8] = z; hx[12] = z;
            }
        }
        __syncthreads();

        // ---- P1: edge-parallel aggregation into smem
        {
            int nend = (n0 + TB < N_NODES) ? n0 + TB : N_NODES;
            int beg = g_row[n0];
            int end = g_row[nend];
            int Et = end - beg;
            int chunk = (Et + 7) >> 3;
            int wb = beg + warp * chunk;
            int we = wb + chunk;
            if (we > end) we = end;

            float2 acc = make_float2(0.f, 0.f);
            int cur = -1;

#pragma unroll 1
            for (int e = wb; e < we; e += 8) {
                int4 ed[8];
#pragma unroll
                for (int j = 0; j < 8; ++j) {
                    int ej = (e + j < we) ? e + j : we - 1;
                    ed[j] = g_edge[ej];
                }
                float2 v[8];
#pragma unroll
                for (int j = 0; j < 8; ++j)
                    v[j] = *reinterpret_cast<const float2*>(
                        xin + (size_t)ed[j].x * D + 2 * lane);
#pragma unroll
                for (int j = 0; j < 8; ++j) {
                    float wt = (e + j < we) ? __int_as_float(ed[j].z) : 0.f;
                    int d = ed[j].y;
                    if (d != cur) {
                        if (cur >= 0) {
                            float* p = h_s + (cur - n0) * HSTR + 2 * lane;
                            atomicAdd(p, acc.x);
                            atomicAdd(p + 1, acc.y);
                        }
                        acc.x = 0.f; acc.y = 0.f;
                        cur = d;
                    }
                    acc.x += v[j].x * wt;
                    acc.y += v[j].y * wt;
                }
            }
            if (cur >= 0) {
                float* p = h_s + (cur - n0) * HSTR + 2 * lane;
                atomicAdd(p, acc.x);
                atomicAdd(p + 1, acc.y);
            }
        }
        __syncthreads();

        // ---- P2: in-place l2norm of aggr cols (warp per 8 rows)
        {
#pragma unroll 1
            for (int j = 0; j < 8; ++j) {
                int r = (warp << 3) + j;
                float a0 = h_s[r * HSTR + lane];
                float a1 = h_s[r * HSTR + lane + 32];
                float ss = a0 * a0 + a1 * a1;
#pragma unroll
                for (int m = 16; m; m >>= 1)
                    ss += __shfl_xor_sync(0xFFFFFFFFu, ss, m);
                float inv = 1.0f / fmaxf(sqrtf(ss), 1e-12f);
                h_s[r * HSTR + lane]      = a0 * inv;
                h_s[r * HSTR + lane + 32] = a1 * inv;
            }
        }
        __syncthreads();

        // ---- P3: GEMM with packed f32x2 FFMA
        u64 acc2[4][2];
#pragma unroll
        for (int i = 0; i < 4; ++i) { acc2[i][0] = bias0; acc2[i][1] = bias1; }

        const float* hbase = h_s + (ty * 4) * HSTR;
#pragma unroll 4
        for (int k = 0; k < 128; k += 4) {
            ulonglong2 wq0 = *reinterpret_cast<const ulonglong2*>(W_s + (k + 0) * 64 + tx * 4);
            ulonglong2 wq1 = *reinterpret_cast<const ulonglong2*>(W_s + (k + 1) * 64 + tx * 4);
            ulonglong2 wq2 = *reinterpret_cast<const ulonglong2*>(W_s + (k + 2) * 64 + tx * 4);
            ulonglong2 wq3 = *reinterpret_cast<const ulonglong2*>(W_s + (k + 3) * 64 + tx * 4);
#pragma unroll
            for (int i = 0; i < 4; ++i) {
                float4 h4 = *reinterpret_cast<const float4*>(hbase + i * HSTR + k);
                u64 hx = bcast2(h4.x);
                acc2[i][0] = fma2(hx, wq0.x, acc2[i][0]);
                acc2[i][1] = fma2(hx, wq0.y, acc2[i][1]);
                u64 hy = bcast2(h4.y);
                acc2[i][0] = fma2(hy, wq1.x, acc2[i][0]);
                acc2[i][1] = fma2(hy, wq1.y, acc2[i][1]);
                u64 hz = bcast2(h4.z);
                acc2[i][0] = fma2(hz, wq2.x, acc2[i][0]);
                acc2[i][1] = fma2(hz, wq2.y, acc2[i][1]);
                u64 hw = bcast2(h4.w);
                acc2[i][0] = fma2(hw, wq3.x, acc2[i][0]);
                acc2[i][1] = fma2(hw, wq3.y, acc2[i][1]);
            }
        }

        // row l2norm across 16 tx threads, store
#pragma unroll
        for (int i = 0; i < 4; ++i) {
            int r = ty * 4 + i;
            int node = n0 + r;
            float2 c0 = unpack2(acc2[i][0]);
            float2 c1 = unpack2(acc2[i][1]);
            float ss = c0.x * c0.x + c0.y * c0.y + c1.x * c1.x + c1.y * c1.y;
#pragma unroll
            for (int m = 8; m; m >>= 1) ss += __shfl_xor_sync(0xFFFFFFFFu, ss, m);
            float inv = 1.0f / fmaxf(sqrtf(ss), 1e-12f);
            if (node < N_NODES) {
                float4 o;
                o.x = c0.x * inv; o.y = c0.y * inv;
                o.z = c1.x * inv; o.w = c1.y * inv;
                *reinterpret_cast<float4*>(xout + (size_t)node * D + tx * 4) = o;
            }
        }
    }
}

// ---------------------------------------------------------------------------
extern "C" void kernel_launch(void* const* d_in, const int* in_sizes, int n_in,
                              void* d_out, int out_size) {
    const float* x  = (const float*)d_in[0];
    const int* ei   = (const int*)d_in[1];
    const float* ew = (const float*)d_in[2];
    const float* W  = (const float*)d_in[3];
    const float* b  = (const float*)d_in[4];
    float* out      = (float*)d_out;

    float *buf0, *buf1;
    int* deg;
    cudaGetSymbolAddress((void**)&buf0, g_buf0);
    cudaGetSymbolAddress((void**)&buf1, g_buf1);
    cudaGetSymbolAddress((void**)&deg, g_deg);

    cudaFuncSetAttribute(layer_kernel,
                         cudaFuncAttributeMaxDynamicSharedMemorySize,
                         SMEM_BYTES);

    const int edge_blocks = (N_EDGES + 255) / 256;
    const int layer_blocks = 148 * 3;

    // CSR build (once per call)
    cudaMemsetAsync(deg, 0, N_NODES * sizeof(int), 0);
    hist_kernel<<<edge_blocks, 256>>>(ei);
    scan_kernel<<<1, SCAN_T>>>();
    permute_kernel<<<edge_blocks, 256>>>(ei, ew);

    const float* cur = x;
    for (int l = 0; l < N_LAYERS; ++l) {
        float* nxt = (l == N_LAYERS - 1) ? out : ((l & 1) ? buf1 : buf0);
        layer_kernel<<<layer_blocks, 256, SMEM_BYTES>>>(
            cur, W + (size_t)l * 2 * D * D, b + (size_t)l * D, nxt);
        cur = nxt;
    }
}

// round 7
// speedup vs baseline: 1.1757x; 1.1757x over previous
#include <cuda_runtime.h>
#include <stdint.h>

#define N_NODES 50000
#define N_EDGES 800000
#define D 64
#define N_LAYERS 12

typedef unsigned long long u64;

__device__ float g_aggr[N_NODES * D];
__device__ float g_buf0[N_NODES * D];
__device__ float g_buf1[N_NODES * D];
// CSR-sorted edge arrays (built once per launch)
__device__ int   g_deg[N_NODES];
__device__ int   g_cur[N_NODES];
__device__ int   g_src[N_EDGES];
__device__ int   g_dst[N_EDGES];
__device__ float g_w[N_EDGES];

// ---------------------------------------------------------------------------
// CSR build: histogram -> scan -> permute (sort edges by dst)
// ---------------------------------------------------------------------------
__global__ void hist_kernel(const int* __restrict__ ei) {
    int e = blockIdx.x * blockDim.x + threadIdx.x;
    if (e < N_EDGES) atomicAdd(&g_deg[ei[N_EDGES + e]], 1);
}

#define SCAN_T 1024
#define SCAN_C 49
__global__ void scan_kernel() {
    __shared__ int part[SCAN_T];
    int t = threadIdx.x;
    int base = t * SCAN_C;
    int s = 0;
#pragma unroll 1
    for (int j = 0; j < SCAN_C; ++j) {
        int idx = base + j;
        if (idx < N_NODES) s += g_deg[idx];
    }
    part[t] = s;
    __syncthreads();
    for (int off = 1; off < SCAN_T; off <<= 1) {
        int v = (t >= off) ? part[t - off] : 0;
        __syncthreads();
        part[t] += v;
        __syncthreads();
    }
    int run = (t > 0) ? part[t - 1] : 0;
#pragma unroll 1
    for (int j = 0; j < SCAN_C; ++j) {
        int idx = base + j;
        if (idx < N_NODES) {
            g_cur[idx] = run;
            run += g_deg[idx];
        }
    }
}

__global__ void permute_kernel(const int* __restrict__ ei,
                               const float* __restrict__ ew) {
    int e = blockIdx.x * blockDim.x + threadIdx.x;
    if (e >= N_EDGES) return;
    int d = ei[N_EDGES + e];
    int pos = atomicAdd(&g_cur[d], 1);
    g_src[pos] = ei[e];
    g_dst[pos] = d;
    g_w[pos] = ew[e];
}

// ---------------------------------------------------------------------------
// Aggregation: warp owns AGG_SPAN consecutive dst-sorted edges. Batches of 8:
// bulk index/weight loads, 8 independent float2 row gathers (MLP=8),
// register segmented sum, red.global flush only on dst change.
// AGG_SPAN=64 -> 12500 warps: fills all 9472 warp slots (occupancy-bound fix).
// ---------------------------------------------------------------------------
#define AGG_SPAN 64
#define N_SPANS (N_EDGES / AGG_SPAN)   // 12500 exactly

__device__ __forceinline__ void flush_v2(float* aggr, int dstn, int lane, float2 a) {
    float* p = aggr + (size_t)dstn * D + 2 * lane;
    u64 gp = (u64)__cvta_generic_to_global(p);
    asm volatile("red.global.add.v2.f32 [%0], {%1,%2};"
                 :: "l"(gp), "f"(a.x), "f"(a.y) : "memory");
}

__global__ void __launch_bounds__(256)
aggregate_kernel(const float* __restrict__ xin, float* __restrict__ aggr) {
    int warp = threadIdx.x >> 5, lane = threadIdx.x & 31;
    int span = blockIdx.x * 8 + warp;
    if (span >= N_SPANS) return;
    int e0 = span * AGG_SPAN;

    float2 acc = make_float2(0.f, 0.f);
    int cur = -1;

#pragma unroll 1
    for (int e = e0; e < e0 + AGG_SPAN; e += 8) {
        int4 i0 = *reinterpret_cast<const int4*>(g_src + e);
        int4 i1 = *reinterpret_cast<const int4*>(g_src + e + 4);
        int4 d0 = *reinterpret_cast<const int4*>(g_dst + e);
        int4 d1 = *reinterpret_cast<const int4*>(g_dst + e + 4);
        float4 w0 = *reinterpret_cast<const float4*>(g_w + e);
        float4 w1 = *reinterpret_cast<const float4*>(g_w + e + 4);
        int idx[8] = {i0.x, i0.y, i0.z, i0.w, i1.x, i1.y, i1.z, i1.w};
        int dst[8] = {d0.x, d0.y, d0.z, d0.w, d1.x, d1.y, d1.z, d1.w};
        float wt[8] = {w0.x, w0.y, w0.z, w0.w, w1.x, w1.y, w1.z, w1.w};

        float2 v[8];
#pragma unroll
        for (int j = 0; j < 8; ++j)
            v[j] = *reinterpret_cast<const float2*>(xin + (size_t)idx[j] * D + 2 * lane);

#pragma unroll
        for (int j = 0; j < 8; ++j) {
            if (dst[j] != cur) {
                if (cur >= 0) flush_v2(aggr, cur, lane, acc);
                acc = make_float2(0.f, 0.f);
                cur = dst[j];
            }
            acc.x += v[j].x * wt[j];
            acc.y += v[j].y * wt[j];
        }
    }
    if (cur >= 0) flush_v2(aggr, cur, lane, acc);
}

// ---------------------------------------------------------------------------
// Update: xout = l2norm( concat(l2norm(aggr), x) @ W + b ), FFMA2 (f32x2) GEMM
// 391 blocks x exactly 2 tiles (balanced), 256 threads, 3 CTA/SM.
// Zeroes aggr rows after read (replaces per-layer memset).
// ---------------------------------------------------------------------------
#define TB 64
#define HSTR 132
#define N_TILES ((N_NODES + TB - 1) / TB)   // 782
#define SMEM_BYTES ((128 * 64 + TB * HSTR) * 4)

__device__ __forceinline__ u64 fma2(u64 a, u64 b, u64 c) {
    u64 d;
    asm("fma.rn.f32x2 %0, %1, %2, %3;" : "=l"(d) : "l"(a), "l"(b), "l"(c));
    return d;
}
__device__ __forceinline__ u64 bcast2(float x) {
    u64 d;
    asm("mov.b64 %0, {%1, %1};" : "=l"(d) : "f"(x));
    return d;
}
__device__ __forceinline__ u64 pack2(float lo, float hi) {
    u64 d;
    asm("mov.b64 %0, {%1, %2};" : "=l"(d) : "f"(lo), "f"(hi));
    return d;
}
__device__ __forceinline__ float2 unpack2(u64 v) {
    float lo, hi;
    asm("mov.b64 {%0, %1}, %2;" : "=f"(lo), "=f"(hi) : "l"(v));
    return make_float2(lo, hi);
}

__global__ void __launch_bounds__(256, 3)
update_kernel(float* __restrict__ aggr,
              const float* __restrict__ xin,
              const float* __restrict__ W,
              const float* __restrict__ b,
              float* __restrict__ xout) {
    extern __shared__ float smem[];
    float* W_s = smem;             // 128*64
    float* h_s = smem + 128 * 64;  // TB x HSTR

    int tid = threadIdx.x;
    int lane = tid & 31;
    int warp = tid >> 5;

    {
        const float4* Wv = reinterpret_cast<const float4*>(W);
        float4* Wsv = reinterpret_cast<float4*>(W_s);
#pragma unroll
        for (int i = 0; i < 8; ++i)
            Wsv[tid + i * 256] = Wv[tid + i * 256];
    }

    int tx = tid & 15, ty = tid >> 4;
    u64 bias0 = pack2(b[tx * 4 + 0], b[tx * 4 + 1]);
    u64 bias1 = pack2(b[tx * 4 + 2], b[tx * 4 + 3]);

    int p1_node = (warp << 3) + (lane >> 2);
    int p1_p = lane & 3;

    for (int tile = blockIdx.x; tile < N_TILES; tile += gridDim.x) {
        __syncthreads();

        // ---- Phase 1: load aggr + x, l2norm(aggr), fill h_s, zero aggr rows
        {
            int node = tile * TB + p1_node;
            float4 a[4], xv[4];
            if (node < N_NODES) {
                const float4* ar = reinterpret_cast<const float4*>(aggr + (size_t)node * D);
                const float4* xr = reinterpret_cast<const float4*>(xin + (size_t)node * D);
#pragma unroll
                for (int j = 0; j < 4; ++j) {
                    a[j]  = ar[p1_p + j * 4];
                    xv[j] = xr[p1_p + j * 4];
                }
                float4 z = make_float4(0.f, 0.f, 0.f, 0.f);
                float4* aw = reinterpret_cast<float4*>(aggr + (size_t)node * D);
#pragma unroll
                for (int j = 0; j < 4; ++j) aw[p1_p + j * 4] = z;
            } else {
#pragma unroll
                for (int j = 0; j < 4; ++j) {
                    a[j] = make_float4(0.f, 0.f, 0.f, 0.f);
                    xv[j] = a[j];
                }
            }
            float ss = 0.f;
#pragma unroll
            for (int j = 0; j < 4; ++j)
                ss += a[j].x * a[j].x + a[j].y * a[j].y
                    + a[j].z * a[j].z + a[j].w * a[j].w;
            ss += __shfl_xor_sync(0xFFFFFFFFu, ss, 1);
            ss += __shfl_xor_sync(0xFFFFFFFFu, ss, 2);
            float inv = 1.0f / fmaxf(sqrtf(ss), 1e-12f);

            float4* hr = reinterpret_cast<float4*>(h_s + p1_node * HSTR);
#pragma unroll
            for (int j = 0; j < 4; ++j) {
                float4 an;
                an.x = a[j].x * inv; an.y = a[j].y * inv;
                an.z = a[j].z * inv; an.w = a[j].w * inv;
                hr[p1_p + j * 4] = an;
                hr[16 + p1_p + j * 4] = xv[j];
            }
        }
        __syncthreads();

        // ---- Phase 2: GEMM with packed f32x2 FFMA
        u64 acc2[4][2];
#pragma unroll
        for (int i = 0; i < 4; ++i) { acc2[i][0] = bias0; acc2[i][1] = bias1; }

        const float* hbase = h_s + (ty * 4) * HSTR;
#pragma unroll 4
        for (int k = 0; k < 128; k += 4) {
            ulonglong2 wq0 = *reinterpret_cast<const ulonglong2*>(W_s + (k + 0) * 64 + tx * 4);
            ulonglong2 wq1 = *reinterpret_cast<const ulonglong2*>(W_s + (k + 1) * 64 + tx * 4);
            ulonglong2 wq2 = *reinterpret_cast<const ulonglong2*>(W_s + (k + 2) * 64 + tx * 4);
            ulonglong2 wq3 = *reinterpret_cast<const ulonglong2*>(W_s + (k + 3) * 64 + tx * 4);
#pragma unroll
            for (int i = 0; i < 4; ++i) {
                float4 h4 = *reinterpret_cast<const float4*>(hbase + i * HSTR + k);
                u64 hx = bcast2(h4.x);
                acc2[i][0] = fma2(hx, wq0.x, acc2[i][0]);
                acc2[i][1] = fma2(hx, wq0.y, acc2[i][1]);
                u64 hy = bcast2(h4.y);
                acc2[i][0] = fma2(hy, wq1.x, acc2[i][0]);
                acc2[i][1] = fma2(hy, wq1.y, acc2[i][1]);
                u64 hz = bcast2(h4.z);
                acc2[i][0] = fma2(hz, wq2.x, acc2[i][0]);
                acc2[i][1] = fma2(hz, wq2.y, acc2[i][1]);
                u64 hw = bcast2(h4.w);
                acc2[i][0] = fma2(hw, wq3.x, acc2[i][0]);
                acc2[i][1] = fma2(hw, wq3.y, acc2[i][1]);
            }
        }

        // ---- Phase 3: row l2norm across 16 tx threads, store
#pragma unroll
        for (int i = 0; i < 4; ++i) {
            int r = ty * 4 + i;
            int node = tile * TB + r;
            float2 c0 = unpack2(acc2[i][0]);
            float2 c1 = unpack2(acc2[i][1]);
            float ss = c0.x * c0.x + c0.y * c0.y + c1.x * c1.x + c1.y * c1.y;
#pragma unroll
            for (int m = 8; m; m >>= 1) ss += __shfl_xor_sync(0xFFFFFFFFu, ss, m);
            float inv = 1.0f / fmaxf(sqrtf(ss), 1e-12f);
            if (node < N_NODES) {
                float4 o;
                o.x = c0.x * inv; o.y = c0.y * inv;
                o.z = c1.x * inv; o.w = c1.y * inv;
                *reinterpret_cast<float4*>(xout + (size_t)node * D + tx * 4) = o;
            }
        }
    }
}

// ---------------------------------------------------------------------------
extern "C" void kernel_launch(void* const* d_in, const int* in_sizes, int n_in,
                              void* d_out, int out_size) {
    const float* x  = (const float*)d_in[0];
    const int* ei   = (const int*)d_in[1];
    const float* ew = (const float*)d_in[2];
    const float* W  = (const float*)d_in[3];
    const float* b  = (const float*)d_in[4];
    float* out      = (float*)d_out;

    float *aggr, *buf0, *buf1;
    int* deg;
    cudaGetSymbolAddress((void**)&aggr, g_aggr);
    cudaGetSymbolAddress((void**)&buf0, g_buf0);
    cudaGetSymbolAddress((void**)&buf1, g_buf1);
    cudaGetSymbolAddress((void**)&deg, g_deg);

    cudaFuncSetAttribute(update_kernel,
                         cudaFuncAttributeMaxDynamicSharedMemorySize,
                         SMEM_BYTES);

    const int edge_blocks = (N_EDGES + 255) / 256;
    const int agg_blocks = (N_SPANS + 7) / 8;   // 1563
    const int upd_blocks = 391;                 // 782 tiles / exactly 2 each

    // CSR build (once per call)
    cudaMemsetAsync(deg, 0, N_NODES * sizeof(int), 0);
    hist_kernel<<<edge_blocks, 256>>>(ei);
    scan_kernel<<<1, SCAN_T>>>();
    permute_kernel<<<edge_blocks, 256>>>(ei, ew);

    // aggr starts zero; update re-zeros it each layer
    cudaMemsetAsync(aggr, 0, (size_t)N_NODES * D * sizeof(float), 0);

    const float* cur = x;
    for (int l = 0; l < N_LAYERS; ++l) {
        aggregate_kernel<<<agg_blocks, 256>>>(cur, aggr);
        float* nxt = (l == N_LAYERS - 1) ? out : ((l & 1) ? buf1 : buf0);
        update_kernel<<<upd_blocks, 256, SMEM_BYTES>>>(
            aggr, cur, W + (size_t)l * 2 * D * D, b + (size_t)l * D, nxt);
        cur = nxt;
    }
}

// round 8
// speedup vs baseline: 1.1902x; 1.0124x over previous
#include <cuda_runtime.h>
#include <stdint.h>

#define N_NODES 50000
#define N_EDGES 800000
#define D 64
#define N_LAYERS 12

typedef unsigned long long u64;

__device__ float g_aggr[N_NODES * D];
__device__ float g_buf0[N_NODES * D];
__device__ float g_buf1[N_NODES * D];
// CSR-sorted edge arrays (built once per launch)
__device__ int   g_deg[N_NODES];
__device__ int   g_cur[N_NODES];
__device__ int   g_src[N_EDGES];
__device__ int   g_dst[N_EDGES];
__device__ float g_w[N_EDGES];

// ---------------------------------------------------------------------------
// CSR build: histogram -> scan -> permute (sort edges by dst)
// ---------------------------------------------------------------------------
__global__ void hist_kernel(const int* __restrict__ ei) {
    int e = blockIdx.x * blockDim.x + threadIdx.x;
    if (e < N_EDGES) atomicAdd(&g_deg[ei[N_EDGES + e]], 1);
}

#define SCAN_T 1024
#define SCAN_C 49
__global__ void scan_kernel() {
    __shared__ int part[SCAN_T];
    int t = threadIdx.x;
    int base = t * SCAN_C;
    int s = 0;
#pragma unroll 1
    for (int j = 0; j < SCAN_C; ++j) {
        int idx = base + j;
        if (idx < N_NODES) s += g_deg[idx];
    }
    part[t] = s;
    __syncthreads();
    for (int off = 1; off < SCAN_T; off <<= 1) {
        int v = (t >= off) ? part[t - off] : 0;
        __syncthreads();
        part[t] += v;
        __syncthreads();
    }
    int run = (t > 0) ? part[t - 1] : 0;
#pragma unroll 1
    for (int j = 0; j < SCAN_C; ++j) {
        int idx = base + j;
        if (idx < N_NODES) {
            g_cur[idx] = run;
            run += g_deg[idx];
        }
    }
}

__global__ void permute_kernel(const int* __restrict__ ei,
                               const float* __restrict__ ew) {
    int e = blockIdx.x * blockDim.x + threadIdx.x;
    if (e >= N_EDGES) return;
    int d = ei[N_EDGES + e];
    int pos = atomicAdd(&g_cur[d], 1);
    g_src[pos] = ei[e];
    g_dst[pos] = d;
    g_w[pos] = ew[e];
}

// ---------------------------------------------------------------------------
// Aggregation: warp owns AGG_SPAN=64 consecutive dst-sorted edges.
// Batches of 16: bulk index/weight loads, 16 independent float2 row gathers
// (MLP=16), register segmented sum, red.global flush only on dst change.
// ---------------------------------------------------------------------------
#define AGG_SPAN 64
#define N_SPANS (N_EDGES / AGG_SPAN)   // 12500 exactly

__device__ __forceinline__ void flush_v2(float* aggr, int dstn, int lane, float2 a) {
    float* p = aggr + (size_t)dstn * D + 2 * lane;
    u64 gp = (u64)__cvta_generic_to_global(p);
    asm volatile("red.global.add.v2.f32 [%0], {%1,%2};"
                 :: "l"(gp), "f"(a.x), "f"(a.y) : "memory");
}

__global__ void __launch_bounds__(256)
aggregate_kernel(const float* __restrict__ xin, float* __restrict__ aggr) {
    int warp = threadIdx.x >> 5, lane = threadIdx.x & 31;
    int span = blockIdx.x * 8 + warp;
    if (span >= N_SPANS) return;
    int e0 = span * AGG_SPAN;

    float2 acc = make_float2(0.f, 0.f);
    int cur = -1;

#pragma unroll 1
    for (int e = e0; e < e0 + AGG_SPAN; e += 16) {
        int4 i0 = *reinterpret_cast<const int4*>(g_src + e);
        int4 i1 = *reinterpret_cast<const int4*>(g_src + e + 4);
        int4 i2 = *reinterpret_cast<const int4*>(g_src + e + 8);
        int4 i3 = *reinterpret_cast<const int4*>(g_src + e + 12);
        int4 d0 = *reinterpret_cast<const int4*>(g_dst + e);
        int4 d1 = *reinterpret_cast<const int4*>(g_dst + e + 4);
        int4 d2 = *reinterpret_cast<const int4*>(g_dst + e + 8);
        int4 d3 = *reinterpret_cast<const int4*>(g_dst + e + 12);
        float4 w0 = *reinterpret_cast<const float4*>(g_w + e);
        float4 w1 = *reinterpret_cast<const float4*>(g_w + e + 4);
        float4 w2 = *reinterpret_cast<const float4*>(g_w + e + 8);
        float4 w3 = *reinterpret_cast<const float4*>(g_w + e + 12);
        int idx[16] = {i0.x, i0.y, i0.z, i0.w, i1.x, i1.y, i1.z, i1.w,
                       i2.x, i2.y, i2.z, i2.w, i3.x, i3.y, i3.z, i3.w};
        int dst[16] = {d0.x, d0.y, d0.z, d0.w, d1.x, d1.y, d1.z, d1.w,
                       d2.x, d2.y, d2.z, d2.w, d3.x, d3.y, d3.z, d3.w};
        float wt[16] = {w0.x, w0.y, w0.z, w0.w, w1.x, w1.y, w1.z, w1.w,
                        w2.x, w2.y, w2.z, w2.w, w3.x, w3.y, w3.z, w3.w};

        float2 v[16];
#pragma unroll
        for (int j = 0; j < 16; ++j)
            v[j] = *reinterpret_cast<const float2*>(xin + (size_t)idx[j] * D + 2 * lane);

#pragma unroll
        for (int j = 0; j < 16; ++j) {
            if (dst[j] != cur) {
                if (cur >= 0) flush_v2(aggr, cur, lane, acc);
                acc = make_float2(0.f, 0.f);
                cur = dst[j];
            }
            acc.x += v[j].x * wt[j];
            acc.y += v[j].y * wt[j];
        }
    }
    if (cur >= 0) flush_v2(aggr, cur, lane, acc);
}

// ---------------------------------------------------------------------------
// Update: xout = l2norm( concat(l2norm(aggr), x) @ W + b ), FFMA2 (f32x2) GEMM
// 391 blocks x exactly 2 tiles, 256 threads, 3 CTA/SM.
// Zeroes aggr rows after read (replaces per-layer memset).
// ---------------------------------------------------------------------------
#define TB 64
#define HSTR 132
#define N_TILES ((N_NODES + TB - 1) / TB)   // 782
#define SMEM_BYTES ((128 * 64 + TB * HSTR) * 4)

__device__ __forceinline__ u64 fma2(u64 a, u64 b, u64 c) {
    u64 d;
    asm("fma.rn.f32x2 %0, %1, %2, %3;" : "=l"(d) : "l"(a), "l"(b), "l"(c));
    return d;
}
__device__ __forceinline__ u64 bcast2(float x) {
    u64 d;
    asm("mov.b64 %0, {%1, %1};" : "=l"(d) : "f"(x));
    return d;
}
__device__ __forceinline__ u64 pack2(float lo, float hi) {
    u64 d;
    asm("mov.b64 %0, {%1, %2};" : "=l"(d) : "f"(lo), "f"(hi));
    return d;
}
__device__ __forceinline__ float2 unpack2(u64 v) {
    float lo, hi;
    asm("mov.b64 {%0, %1}, %2;" : "=f"(lo), "=f"(hi) : "l"(v));
    return make_float2(lo, hi);
}

__global__ void __launch_bounds__(256, 3)
update_kernel(float* __restrict__ aggr,
              const float* __restrict__ xin,
              const float* __restrict__ W,
              const float* __restrict__ b,
              float* __restrict__ xout) {
    extern __shared__ float smem[];
    float* W_s = smem;             // 128*64
    float* h_s = smem + 128 * 64;  // TB x HSTR

    int tid = threadIdx.x;
    int lane = tid & 31;
    int warp = tid >> 5;

    {
        const float4* Wv = reinterpret_cast<const float4*>(W);
        float4* Wsv = reinterpret_cast<float4*>(W_s);
#pragma unroll
        for (int i = 0; i < 8; ++i)
            Wsv[tid + i * 256] = Wv[tid + i * 256];
    }

    int tx = tid & 15, ty = tid >> 4;
    u64 bias0 = pack2(b[tx * 4 + 0], b[tx * 4 + 1]);
    u64 bias1 = pack2(b[tx * 4 + 2], b[tx * 4 + 3]);

    int p1_node = (warp << 3) + (lane >> 2);
    int p1_p = lane & 3;

    for (int tile = blockIdx.x; tile < N_TILES; tile += gridDim.x) {
        __syncthreads();

        // ---- Phase 1: load aggr + x, l2norm(aggr), fill h_s, zero aggr rows
        {
            int node = tile * TB + p1_node;
            float4 a[4], xv[4];
            if (node < N_NODES) {
                const float4* ar = reinterpret_cast<const float4*>(aggr + (size_t)node * D);
                const float4* xr = reinterpret_cast<const float4*>(xin + (size_t)node * D);
#pragma unroll
                for (int j = 0; j < 4; ++j) {
                    a[j]  = ar[p1_p + j * 4];
                    xv[j] = xr[p1_p + j * 4];
                }
                float4 z = make_float4(0.f, 0.f, 0.f, 0.f);
                float4* aw = reinterpret_cast<float4*>(aggr + (size_t)node * D);
#pragma unroll
                for (int j = 0; j < 4; ++j) aw[p1_p + j * 4] = z;
            } else {
#pragma unroll
                for (int j = 0; j < 4; ++j) {
                    a[j] = make_float4(0.f, 0.f, 0.f, 0.f);
                    xv[j] = a[j];
                }
            }
            float ss = 0.f;
#pragma unroll
            for (int j = 0; j < 4; ++j)
                ss += a[j].x * a[j].x + a[j].y * a[j].y
                    + a[j].z * a[j].z + a[j].w * a[j].w;
            ss += __shfl_xor_sync(0xFFFFFFFFu, ss, 1);
            ss += __shfl_xor_sync(0xFFFFFFFFu, ss, 2);
            float inv = 1.0f / fmaxf(sqrtf(ss), 1e-12f);

            float4* hr = reinterpret_cast<float4*>(h_s + p1_node * HSTR);
#pragma unroll
            for (int j = 0; j < 4; ++j) {
                float4 an;
                an.x = a[j].x * inv; an.y = a[j].y * inv;
                an.z = a[j].z * inv; an.w = a[j].w * inv;
                hr[p1_p + j * 4] = an;
                hr[16 + p1_p + j * 4] = xv[j];
            }
        }
        __syncthreads();

        // ---- Phase 2: GEMM with packed f32x2 FFMA
        u64 acc2[4][2];
#pragma unroll
        for (int i = 0; i < 4; ++i) { acc2[i][0] = bias0; acc2[i][1] = bias1; }

        const float* hbase = h_s + (ty * 4) * HSTR;
#pragma unroll 4
        for (int k = 0; k < 128; k += 4) {
            ulonglong2 wq0 = *reinterpret_cast<const ulonglong2*>(W_s + (k + 0) * 64 + tx * 4);
            ulonglong2 wq1 = *reinterpret_cast<const ulonglong2*>(W_s + (k + 1) * 64 + tx * 4);
            ulonglong2 wq2 = *reinterpret_cast<const ulonglong2*>(W_s + (k + 2) * 64 + tx * 4);
            ulonglong2 wq3 = *reinterpret_cast<const ulonglong2*>(W_s + (k + 3) * 64 + tx * 4);
#pragma unroll
            for (int i = 0; i < 4; ++i) {
                float4 h4 = *reinterpret_cast<const float4*>(hbase + i * HSTR + k);
                u64 hx = bcast2(h4.x);
                acc2[i][0] = fma2(hx, wq0.x, acc2[i][0]);
                acc2[i][1] = fma2(hx, wq0.y, acc2[i][1]);
                u64 hy = bcast2(h4.y);
                acc2[i][0] = fma2(hy, wq1.x, acc2[i][0]);
                acc2[i][1] = fma2(hy, wq1.y, acc2[i][1]);
                u64 hz = bcast2(h4.z);
                acc2[i][0] = fma2(hz, wq2.x, acc2[i][0]);
                acc2[i][1] = fma2(hz, wq2.y, acc2[i][1]);
                u64 hw = bcast2(h4.w);
                acc2[i][0] = fma2(hw, wq3.x, acc2[i][0]);
                acc2[i][1] = fma2(hw, wq3.y, acc2[i][1]);
            }
        }

        // ---- Phase 3: row l2norm across 16 tx threads, store
#pragma unroll
        for (int i = 0; i < 4; ++i) {
            int r = ty * 4 + i;
            int node = tile * TB + r;
            float2 c0 = unpack2(acc2[i][0]);
            float2 c1 = unpack2(acc2[i][1]);
            float ss = c0.x * c0.x + c0.y * c0.y + c1.x * c1.x + c1.y * c1.y;
#pragma unroll
            for (int m = 8; m; m >>= 1) ss += __shfl_xor_sync(0xFFFFFFFFu, ss, m);
            float inv = 1.0f / fmaxf(sqrtf(ss), 1e-12f);
            if (node < N_NODES) {
                float4 o;
                o.x = c0.x * inv; o.y = c0.y * inv;
                o.z = c1.x * inv; o.w = c1.y * inv;
                *reinterpret_cast<float4*>(xout + (size_t)node * D + tx * 4) = o;
            }
        }
    }
}

// ---------------------------------------------------------------------------
extern "C" void kernel_launch(void* const* d_in, const int* in_sizes, int n_in,
                              void* d_out, int out_size) {
    const float* x  = (const float*)d_in[0];
    const int* ei   = (const int*)d_in[1];
    const float* ew = (const float*)d_in[2];
    const float* W  = (const float*)d_in[3];
    const float* b  = (const float*)d_in[4];
    float* out      = (float*)d_out;

    float *aggr, *buf0, *buf1;
    int* deg;
    cudaGetSymbolAddress((void**)&aggr, g_aggr);
    cudaGetSymbolAddress((void**)&buf0, g_buf0);
    cudaGetSymbolAddress((void**)&buf1, g_buf1);
    cudaGetSymbolAddress((void**)&deg, g_deg);

    cudaFuncSetAttribute(update_kernel,
                         cudaFuncAttributeMaxDynamicSharedMemorySize,
                         SMEM_BYTES);

    const int edge_blocks = (N_EDGES + 255) / 256;
    const int agg_blocks = (N_SPANS + 7) / 8;   // 1563
    const int upd_blocks = 391;                 // 782 tiles / exactly 2 each

    // CSR build (once per call)
    cudaMemsetAsync(deg, 0, N_NODES * sizeof(int), 0);
    hist_kernel<<<edge_blocks, 256>>>(ei);
    scan_kernel<<<1, SCAN_T>>>();
    permute_kernel<<<edge_blocks, 256>>>(ei, ew);

    // aggr starts zero; update re-zeros it each layer
    cudaMemsetAsync(aggr, 0, (size_t)N_NODES * D * sizeof(float), 0);

    const float* cur = x;
    for (int l = 0; l < N_LAYERS; ++l) {
        aggregate_kernel<<<agg_blocks, 256>>>(cur, aggr);
        float* nxt = (l == N_LAYERS - 1) ? out : ((l & 1) ? buf1 : buf0);
        update_kernel<<<upd_blocks, 256, SMEM_BYTES>>>(
            aggr, cur, W + (size_t)l * 2 * D * D, b + (size_t)l * D, nxt);
        cur = nxt;
    }
}